// round 1
// baseline (speedup 1.0000x reference)
#include <cuda_runtime.h>

#define N_NODE 50000
#define N_EDGE 800000
#define D_FEAT 64
#define N_M    11
#define DEPTH  3

// ---------------- device scratch (no allocations allowed) ----------------
__device__ float g_y[3][N_NODE * D_FEAT];   // S x, S^2 x, S^3 x
__device__ float g_deg[N_NODE];             // degree, then dinv in-place
__device__ float g_val[N_EDGE];             // normalized edge weights
__device__ float g_q[16];                   // q[L][k], L,k in 0..3

// ---------------- zero scratch (y buffers + deg) ----------------
__global__ __launch_bounds__(256) void zero_kernel() {
    unsigned i = blockIdx.x * blockDim.x + threadIdx.x;
    const unsigned tot = 3u * N_NODE * D_FEAT;   // 9,600,000
    if (i < tot) ((float*)g_y)[i] = 0.0f;
    if (i < N_NODE) g_deg[i] = 0.0f;
}

// ---------------- polynomial coefficient table ----------------
// Every xs_hist[L][m] = sum_k p[L][m][k] * S^k x (linearity of the recurrence,
// and xs0[m] == x for all m). l=-1, r=1 so (l+r)=0, (r-l)=2.
__global__ void coeff_kernel(const float* __restrict__ alphas,
                             const float* __restrict__ w,
                             const float* __restrict__ a_arr,
                             const float* __restrict__ b_arr) {
    if (threadIdx.x != 0 || blockIdx.x != 0) return;
    double q[4][4] = {};
    for (int m = 0; m < N_M; m++) {
        double a = a_arr[m], b = b_arr[m];
        double p[4][4] = {};
        p[0][0] = 1.0;
        double coef1 = (a - b) * 0.5;          // (a-b)/2, (l+r)=0 term vanishes
        double coef2 = (a + b + 2.0) * 0.5;    // (a+b+2)/(r-l)
        double al0 = alphas[0 * N_M + m];
        p[1][0] = al0 * coef1;
        p[1][1] = al0 * coef2;
        for (int L = 2; L <= DEPTH; L++) {
            double Lf = (double)L;
            double coef_l    = 2.0 * Lf * (Lf + a + b) * (2.0 * Lf - 2.0 + a + b);
            double c_lm1_1   = (2.0 * Lf + a + b - 1.0) * (2.0 * Lf + a + b) * (2.0 * Lf + a + b - 2.0);
            double c_lm1_2   = (2.0 * Lf + a + b - 1.0) * (a * a - b * b);
            double c_lm2     = 2.0 * (Lf - 1.0 + a) * (Lf - 1.0 + b) * (2.0 * Lf + a + b);
            double alL   = alphas[(L - 1) * N_M + m];
            double alLm1 = alphas[(L - 2) * N_M + m];
            double tmp1 = alL * (c_lm1_1 / coef_l);          // == tmp1_2 since 2/(r-l)=1
            double tmp2 = alL * (c_lm1_2 / coef_l);          // == tmp2_2 since (r+l)=0
            double tmp3 = alL * alLm1 * (c_lm2 / coef_l);
            for (int k = 0; k <= L; k++) {
                double t = 0.0;
                if (k > 0) t += tmp1 * p[L - 1][k - 1];
                t -= tmp2 * p[L - 1][k];
                t -= tmp3 * p[L - 2][k];
                p[L][k] = t;
            }
        }
        double wm = w[m];
        for (int L = 0; L < 4; L++)
            for (int k = 0; k < 4; k++)
                q[L][k] += wm * p[L][k];
    }
    for (int i = 0; i < 16; i++) g_q[i] = (float)q[i / 4][i % 4];
}

// ---------------- degree / dinv / edge values ----------------
__global__ __launch_bounds__(256) void deg_kernel(const int* __restrict__ ei) {
    unsigned e = blockIdx.x * blockDim.x + threadIdx.x;
    if (e < N_EDGE) atomicAdd(&g_deg[ei[e]], 1.0f);
}

__global__ __launch_bounds__(256) void dinv_kernel() {
    unsigned n = blockIdx.x * blockDim.x + threadIdx.x;
    if (n < N_NODE) {
        float d = g_deg[n];
        if (d < 0.5f) d += 1.0f;
        g_deg[n] = rsqrtf(d);
    }
}

__global__ __launch_bounds__(256) void val_kernel(const int* __restrict__ ei,
                                                  const float* __restrict__ attr) {
    unsigned e = blockIdx.x * blockDim.x + threadIdx.x;
    if (e < N_EDGE)
        g_val[e] = g_deg[ei[e]] * attr[e] * g_deg[ei[e + N_EDGE]];
}

// ---------------- SpMM: y[row] += val * x[col], 16 threads per edge ----------------
// stage 0: read external x, write g_y[0]; stage k: read g_y[k-1], write g_y[k].
__global__ __launch_bounds__(256) void spmm_kernel(const int* __restrict__ ei,
                                                    const float4* __restrict__ xext,
                                                    int stage) {
    unsigned gid = blockIdx.x * blockDim.x + threadIdx.x;
    unsigned e = gid >> 4;
    if (e >= N_EDGE) return;
    unsigned lane = gid & 15u;

    const float4* __restrict__ xin =
        (stage == 0) ? xext : (const float4*)g_y[stage - 1];
    float4* yout = (float4*)g_y[stage];

    int r = __ldg(ei + e);
    int c = __ldg(ei + e + N_EDGE);
    float v = __ldg(g_val + e);
    float4 xv = __ldg(xin + (unsigned)c * 16u + lane);

    float4* dst = yout + (unsigned)r * 16u + lane;
    asm volatile("red.global.add.v4.f32 [%0], {%1, %2, %3, %4};"
                 :: "l"(dst),
                    "f"(v * xv.x), "f"(v * xv.y), "f"(v * xv.z), "f"(v * xv.w)
                 : "memory");
}

// ---------------- combine: out[n,L,:] = sum_k q[L][k] * (S^k x)[n,:] ----------------
__global__ __launch_bounds__(256) void combine_kernel(const float4* __restrict__ x,
                                                       float4* __restrict__ out) {
    unsigned gid = blockIdx.x * blockDim.x + threadIdx.x;   // N_NODE*16 threads
    if (gid >= (unsigned)N_NODE * 16u) return;
    unsigned n = gid >> 4, lane = gid & 15u;

    float4 x0 = __ldg(x + gid);
    float4 a1 = ((const float4*)g_y[0])[gid];
    float4 a2 = ((const float4*)g_y[1])[gid];
    float4 a3 = ((const float4*)g_y[2])[gid];

    float q00 = g_q[0];
    float q10 = g_q[4],  q11 = g_q[5];
    float q20 = g_q[8],  q21 = g_q[9],  q22 = g_q[10];
    float q30 = g_q[12], q31 = g_q[13], q32 = g_q[14], q33 = g_q[15];

    float4 o0, o1, o2, o3;
    o0.x = q00 * x0.x; o0.y = q00 * x0.y; o0.z = q00 * x0.z; o0.w = q00 * x0.w;

    o1.x = q10 * x0.x + q11 * a1.x;
    o1.y = q10 * x0.y + q11 * a1.y;
    o1.z = q10 * x0.z + q11 * a1.z;
    o1.w = q10 * x0.w + q11 * a1.w;

    o2.x = q20 * x0.x + q21 * a1.x + q22 * a2.x;
    o2.y = q20 * x0.y + q21 * a1.y + q22 * a2.y;
    o2.z = q20 * x0.z + q21 * a1.z + q22 * a2.z;
    o2.w = q20 * x0.w + q21 * a1.w + q22 * a2.w;

    o3.x = q30 * x0.x + q31 * a1.x + q32 * a2.x + q33 * a3.x;
    o3.y = q30 * x0.y + q31 * a1.y + q32 * a2.y + q33 * a3.y;
    o3.z = q30 * x0.z + q31 * a1.z + q32 * a2.z + q33 * a3.z;
    o3.w = q30 * x0.w + q31 * a1.w + q32 * a2.w + q33 * a3.w;

    // out shape (N_NODE, 4, 64) f32 -> float4 index n*64 + L*16 + lane
    unsigned base = n * 64u + lane;
    out[base + 0u * 16u] = o0;
    out[base + 1u * 16u] = o1;
    out[base + 2u * 16u] = o2;
    out[base + 3u * 16u] = o3;
}

// ---------------- launch ----------------
extern "C" void kernel_launch(void* const* d_in, const int* in_sizes, int n_in,
                              void* d_out, int out_size) {
    const float* x      = (const float*)d_in[0];
    const int*   ei     = (const int*)  d_in[1];
    const float* attr   = (const float*)d_in[2];
    const float* alphas = (const float*)d_in[3];
    const float* w      = (const float*)d_in[4];
    const float* a_arr  = (const float*)d_in[5];
    const float* b_arr  = (const float*)d_in[6];
    float* out = (float*)d_out;

    zero_kernel<<<(3u * N_NODE * D_FEAT + 255) / 256, 256>>>();
    coeff_kernel<<<1, 32>>>(alphas, w, a_arr, b_arr);
    deg_kernel<<<(N_EDGE + 255) / 256, 256>>>(ei);
    dinv_kernel<<<(N_NODE + 255) / 256, 256>>>();
    val_kernel<<<(N_EDGE + 255) / 256, 256>>>(ei, attr);

    const unsigned spmm_threads = (unsigned)N_EDGE * 16u;   // 12.8M
    spmm_kernel<<<(spmm_threads + 255) / 256, 256>>>(ei, (const float4*)x, 0);
    spmm_kernel<<<(spmm_threads + 255) / 256, 256>>>(ei, (const float4*)x, 1);
    spmm_kernel<<<(spmm_threads + 255) / 256, 256>>>(ei, (const float4*)x, 2);

    combine_kernel<<<((unsigned)N_NODE * 16u + 255) / 256, 256>>>(
        (const float4*)x, (float4*)out);
}